// round 1
// baseline (speedup 1.0000x reference)
#include <cuda_runtime.h>
#include <cuda_bf16.h>
#include <math.h>

// ---------------- problem dims ----------------
#define BATCH   1024
#define TLEN    16000
#define NFFT    400
#define HOP     200
#define NBINS   201
#define NMELS   128
#define NFRAMES 81          // 1 + (16400-400)/200
#define TSTEPS  79          // after conv k=3 VALID
#define HID     128
#define G4      512
#define R1      (BATCH*NFRAMES)   // 82944
#define R2      (BATCH*TSTEPS)    // 80896

// ---------------- scratch (device globals; no runtime alloc allowed) ----------------
__device__ float  d_hann[NFFT];
__device__ float2 d_tab[NFFT];             // (cos, sin) of 2*pi*m/400
__device__ float  d_melfb[NBINS*NMELS];    // [k][m]
__device__ float  d_Wr[384*128];           // conv weights reordered [q=(kk*128+i)][o]
__device__ float  d_power[R1*NBINS];
__device__ float  d_mel[R1*NMELS];         // (B, 81, 128) frame-major
__device__ float  d_conv[R2*128];          // (B, 79, 128)
__device__ float  d_g1[R2*G4];
__device__ float  d_h1[R2*128];
__device__ float  d_g2[R2*G4];
__device__ float  d_h2[R2*128];
__device__ float  d_hmean[BATCH*128];
__device__ float  d_hfc[BATCH*128];

// ---------------- activations (accurate fast-math, no tanh.approx) ----------------
__device__ __forceinline__ float sigf(float x) {
    return 1.0f / (1.0f + __expf(-x));
}
__device__ __forceinline__ float tanhf_acc(float x) {
    float t = __expf(-2.0f * fabsf(x));       // in (0,1], never overflows
    float r = (1.0f - t) / (1.0f + t);
    return copysignf(r, x);
}

// ---------------- precompute tables + conv weight reorder ----------------
__global__ void k_precompute(const float* __restrict__ conv_w) {
    int tid = threadIdx.x;
    for (int n = tid; n < NFFT; n += blockDim.x) {
        double th = 2.0 * M_PI * (double)n / 400.0;
        d_hann[n] = (float)(0.5 - 0.5 * cos(th));
        d_tab[n]  = make_float2((float)cos(th), (float)sin(th));
    }
    const double mel_max = 2595.0 * log10(1.0 + 8000.0 / 700.0);
    for (int idx = tid; idx < NBINS * NMELS; idx += blockDim.x) {
        int k = idx >> 7, m = idx & 127;
        double freq = 40.0 * (double)k;
        double f0 = 700.0 * (pow(10.0, (mel_max * (double)(m    ) / 129.0) / 2595.0) - 1.0);
        double f1 = 700.0 * (pow(10.0, (mel_max * (double)(m + 1) / 129.0) / 2595.0) - 1.0);
        double f2 = 700.0 * (pow(10.0, (mel_max * (double)(m + 2) / 129.0) / 2595.0) - 1.0);
        double dn = (freq - f0) / (f1 - f0);
        double up = (f2 - freq) / (f2 - f1);
        double v  = dn < up ? dn : up;
        if (v < 0.0) v = 0.0;
        d_melfb[idx] = (float)v;
    }
    // conv_w (o,i,kk) -> Wr[(kk*128+i)*128 + o]
    for (int idx = tid; idx < 384 * 128; idx += blockDim.x) {
        int o = idx & 127, q = idx >> 7;
        int kk = q >> 7, i = q & 127;
        d_Wr[idx] = conv_w[o * 384 + i * 3 + kk];
    }
}

// ---------------- windowed-frame DFT -> power spectrum ----------------
__global__ void k_dft(const float* __restrict__ x) {
    __shared__ float  xw[NFFT];
    __shared__ float2 tab[NFFT];
    int f = blockIdx.x, b = blockIdx.y, tid = threadIdx.x;
    for (int n = tid; n < NFFT; n += 256) {
        tab[n] = d_tab[n];
        int p = f * HOP + n - 200;                     // reflect pad 200
        int i = (p < 0) ? -p : ((p >= TLEN) ? (2 * TLEN - 2 - p) : p);
        xw[n] = x[b * TLEN + i] * d_hann[n];
    }
    __syncthreads();
    int k = tid;
    if (k < NBINS) {
        float c = 0.f, s = 0.f;
        int idx = 0;
        #pragma unroll 8
        for (int n = 0; n < NFFT; n++) {
            float2 t = tab[idx];
            float  v = xw[n];
            c += v * t.x;
            s += v * t.y;
            idx += k; if (idx >= NFFT) idx -= NFFT;
        }
        d_power[(b * NFRAMES + f) * NBINS + k] = c * c + s * s;
    }
}

// ---------------- generic tiled SGEMM: C = A(MxK) @ B(KxN) [+ bias] ----------------
// A row r element k at offset r*lda + (rowdiv? (r/rowdiv)*rowextra : 0) + k
__global__ void k_sgemm(const float* __restrict__ A, const float* __restrict__ Bm,
                        float* __restrict__ C, const float* __restrict__ bias,
                        int M, int N, int K, int lda, int rowdiv, int rowextra) {
    __shared__ float As[8][68];   // padded (bank conflicts) but rows stay 16B-aligned
    __shared__ float Bs[8][64];
    int tid = threadIdx.x;                 // 128 threads
    int m0 = blockIdx.y * 64, n0 = blockIdx.x * 64;
    int tm = tid & 15;                     // 16 groups of 4 rows
    int tn = tid >> 4;                     // 8 groups of 8 cols
    float acc[4][8];
    #pragma unroll
    for (int i = 0; i < 4; i++)
        #pragma unroll
        for (int j = 0; j < 8; j++) acc[i][j] = 0.f;

    for (int kk = 0; kk < K; kk += 8) {
        #pragma unroll
        for (int i = 0; i < 4; i++) {
            int l = tid + i * 128;
            int m = l >> 3, k = l & 7;
            int gm = m0 + m, gk = kk + k;
            float v = 0.f;
            if (gm < M && gk < K) {
                int off = gm * lda + gk;
                if (rowdiv) off += (gm / rowdiv) * rowextra;
                v = A[off];
            }
            As[k][m] = v;
        }
        #pragma unroll
        for (int i = 0; i < 4; i++) {
            int l = tid + i * 128;
            int k = l >> 6, n = l & 63;
            int gk = kk + k, gn = n0 + n;
            Bs[k][n] = (gk < K && gn < N) ? Bm[gk * N + gn] : 0.f;
        }
        __syncthreads();
        #pragma unroll
        for (int k = 0; k < 8; k++) {
            float a[4], bv[8];
            #pragma unroll
            for (int i = 0; i < 4; i++) a[i] = As[k][tm * 4 + i];
            #pragma unroll
            for (int j = 0; j < 8; j++) bv[j] = Bs[k][tn * 8 + j];
            #pragma unroll
            for (int i = 0; i < 4; i++)
                #pragma unroll
                for (int j = 0; j < 8; j++) acc[i][j] += a[i] * bv[j];
        }
        __syncthreads();
    }
    #pragma unroll
    for (int i = 0; i < 4; i++) {
        int gm = m0 + tm * 4 + i;
        if (gm >= M) continue;
        #pragma unroll
        for (int j = 0; j < 8; j++) {
            int gn = n0 + tn * 8 + j;
            if (gn < N) {
                float v = acc[i][j];
                if (bias) v += bias[gn];
                C[gm * N + gn] = v;
            }
        }
    }
}

// ---------------- persistent per-block LSTM layer (8 batch rows / block) ----------------
__global__ void k_lstm(const float* __restrict__ gx, const float* __restrict__ U,
                       float* __restrict__ hout) {
    __shared__ float hb[8][128];
    __shared__ float cb[8][128];
    __shared__ float gb[8][G4];
    int tid = threadIdx.x;                 // 512 threads
    int b0 = blockIdx.x * 8;
    for (int i = tid; i < 8 * 128; i += 512) { (&hb[0][0])[i] = 0.f; (&cb[0][0])[i] = 0.f; }
    __syncthreads();

    for (int t = 0; t < TSTEPS; t++) {
        int j = tid;
        float acc[8];
        #pragma unroll
        for (int r = 0; r < 8; r++)
            acc[r] = gx[((b0 + r) * TSTEPS + t) * G4 + j];
        #pragma unroll 4
        for (int k = 0; k < 128; k += 4) {
            float u0 = U[(k + 0) * G4 + j];
            float u1 = U[(k + 1) * G4 + j];
            float u2 = U[(k + 2) * G4 + j];
            float u3 = U[(k + 3) * G4 + j];
            #pragma unroll
            for (int r = 0; r < 8; r++) {
                float4 h4 = *reinterpret_cast<const float4*>(&hb[r][k]);
                acc[r] += h4.x * u0 + h4.y * u1 + h4.z * u2 + h4.w * u3;
            }
        }
        #pragma unroll
        for (int r = 0; r < 8; r++) gb[r][j] = acc[r];
        __syncthreads();
        #pragma unroll
        for (int s = 0; s < 2; s++) {
            int ui = tid + s * 512;        // 1024 units = 8 rows * 128
            int r = ui >> 7, col = ui & 127;
            float gi = gb[r][col];
            float gf = gb[r][128 + col];
            float gg = gb[r][256 + col];
            float go = gb[r][384 + col];
            float i_ = sigf(gi), f_ = sigf(gf), g_ = tanhf_acc(gg), o_ = sigf(go);
            float c = f_ * cb[r][col] + i_ * g_;
            float h = o_ * tanhf_acc(c);
            cb[r][col] = c;
            hb[r][col] = h;
            hout[((b0 + r) * TSTEPS + t) * 128 + col] = h;
        }
        __syncthreads();
    }
}

// ---------------- time-mean over h2 ----------------
__global__ void k_mean(const float* __restrict__ h2) {
    int b = blockIdx.x, k = threadIdx.x;   // 128 threads
    float s = 0.f;
    for (int t = 0; t < TSTEPS; t++)
        s += h2[(b * TSTEPS + t) * 128 + k];
    d_hmean[b * 128 + k] = s * (1.0f / (float)TSTEPS);
}

// ---------------- launch ----------------
extern "C" void kernel_launch(void* const* d_in, const int* in_sizes, int n_in,
                              void* d_out, int out_size) {
    const float* x      = (const float*)d_in[0];
    const float* conv_w = (const float*)d_in[1];
    const float* conv_b = (const float*)d_in[2];
    const float* W1     = (const float*)d_in[3];
    const float* U1     = (const float*)d_in[4];
    const float* b1     = (const float*)d_in[5];
    const float* W2     = (const float*)d_in[6];
    const float* U2     = (const float*)d_in[7];
    const float* b2     = (const float*)d_in[8];
    const float* fc1_w  = (const float*)d_in[9];
    const float* fc1_b  = (const float*)d_in[10];
    const float* proj_w = (const float*)d_in[11];
    const float* proj_b = (const float*)d_in[12];
    float* out = (float*)d_out;

    float *p_power, *p_melfb, *p_mel, *p_Wr, *p_conv, *p_g1, *p_h1, *p_g2, *p_h2, *p_hmean, *p_hfc;
    cudaGetSymbolAddress((void**)&p_power, d_power);
    cudaGetSymbolAddress((void**)&p_melfb, d_melfb);
    cudaGetSymbolAddress((void**)&p_mel,   d_mel);
    cudaGetSymbolAddress((void**)&p_Wr,    d_Wr);
    cudaGetSymbolAddress((void**)&p_conv,  d_conv);
    cudaGetSymbolAddress((void**)&p_g1,    d_g1);
    cudaGetSymbolAddress((void**)&p_h1,    d_h1);
    cudaGetSymbolAddress((void**)&p_g2,    d_g2);
    cudaGetSymbolAddress((void**)&p_h2,    d_h2);
    cudaGetSymbolAddress((void**)&p_hmean, d_hmean);
    cudaGetSymbolAddress((void**)&p_hfc,   d_hfc);

    k_precompute<<<1, 256>>>(conv_w);

    k_dft<<<dim3(NFRAMES, BATCH), 256>>>(x);

    // mel = power (R1 x 201) @ melfb (201 x 128)
    k_sgemm<<<dim3(2, R1 / 64), 128>>>(p_power, p_melfb, p_mel, nullptr,
                                       R1, NMELS, NBINS, NBINS, 0, 0);
    // conv = mel-window (R2 x 384) @ Wr (384 x 128) + conv_b   (row remap for overlap)
    k_sgemm<<<dim3(2, R2 / 64), 128>>>(p_mel, p_Wr, p_conv, conv_b,
                                       R2, 128, 384, 128, TSTEPS, 2 * 128);
    // g1 = conv (R2 x 128) @ W1 (128 x 512) + b1
    k_sgemm<<<dim3(8, R2 / 64), 128>>>(p_conv, W1, p_g1, b1,
                                       R2, G4, 128, 128, 0, 0);
    k_lstm<<<BATCH / 8, 512>>>(p_g1, U1, p_h1);

    // g2 = h1 (R2 x 128) @ W2 + b2
    k_sgemm<<<dim3(8, R2 / 64), 128>>>(p_h1, W2, p_g2, b2,
                                       R2, G4, 128, 128, 0, 0);
    k_lstm<<<BATCH / 8, 512>>>(p_g2, U2, p_h2);

    k_mean<<<BATCH, 128>>>(p_h2);

    // hfc = hmean (1024 x 128) @ fc1_w + fc1_b   (mean commutes with linear)
    k_sgemm<<<dim3(2, BATCH / 64), 128>>>(p_hmean, fc1_w, p_hfc, fc1_b,
                                          BATCH, 128, 128, 128, 0, 0);
    // out = hfc (1024 x 128) @ proj_w (128 x 35) + proj_b
    k_sgemm<<<dim3(1, BATCH / 64), 128>>>(p_hfc, proj_w, out, proj_b,
                                          BATCH, 35, 128, 128, 0, 0);
}

// round 2
// speedup vs baseline: 3.1755x; 3.1755x over previous
#include <cuda_runtime.h>
#include <cuda_bf16.h>
#include <math.h>

// ---------------- problem dims ----------------
#define BATCH   1024
#define TLEN    16000
#define NFFT    400
#define HOP     200
#define NBINS   201
#define NMELS   128
#define NFRAMES 81
#define TSTEPS  79
#define HID     128
#define G4      512
#define R1      (BATCH*NFRAMES)   // 82944 = 128*648
#define R2      (BATCH*TSTEPS)    // 80896 = 128*632

// Kp (padded K, mult of 32) per GEMM
#define KP_DFT  416   // K=400
#define KP_MEL  224   // K=201
#define KP_CONV 384   // K=384
#define KP_G    128   // K=128
#define NP_DFT  448   // N=402 padded to 64-mult

// ---------------- scratch (device globals; no runtime alloc) ----------------
__device__ float          d_hann[NFFT];
__device__ __nv_bfloat16  d_A2dft[(size_t)R1 * 2 * KP_DFT];
__device__ __nv_bfloat16  d_B2dft[(size_t)NP_DFT * 2 * KP_DFT];
__device__ __nv_bfloat16  d_A2mel[(size_t)R1 * 2 * KP_MEL];
__device__ __nv_bfloat16  d_B2mel[(size_t)128 * 2 * KP_MEL];
__device__ float          d_mel[(size_t)R1 * NMELS];
__device__ __nv_bfloat16  d_A2conv[(size_t)R2 * 2 * KP_CONV];
__device__ __nv_bfloat16  d_B2conv[(size_t)128 * 2 * KP_CONV];
__device__ __nv_bfloat16  d_A2g[(size_t)R2 * 2 * KP_G];
__device__ __nv_bfloat16  d_B2W1[(size_t)G4 * 2 * KP_G];
__device__ __nv_bfloat16  d_B2W2[(size_t)G4 * 2 * KP_G];
__device__ float          d_g[(size_t)R2 * G4];
__device__ __nv_bfloat16  d_h1s[(size_t)R2 * 2 * KP_G];
__device__ float          d_h2[(size_t)R2 * HID];
__device__ float          d_hmean[BATCH * 128];
__device__ float          d_hfc[BATCH * 128];

// ---------------- helpers ----------------
__device__ __forceinline__ float sigf(float x) { return 1.0f / (1.0f + __expf(-x)); }
__device__ __forceinline__ float tanhf_acc(float x) {
    float t = __expf(-2.0f * fabsf(x));
    float r = (1.0f - t) / (1.0f + t);
    return copysignf(r, x);
}
__device__ __forceinline__ void splitw(__nv_bfloat16* P, size_t base, int KpOut, int k, float v) {
    __nv_bfloat16 h = __float2bfloat16(v);
    P[base + k] = h;
    P[base + KpOut + k] = __float2bfloat16(v - __bfloat162float(h));
}

// ---------------- precompute: tables + all constant B2 packs ----------------
__global__ void k_precompute(const float* __restrict__ conv_w,
                             const float* __restrict__ W1,
                             const float* __restrict__ W2) {
    int tid = blockIdx.x * blockDim.x + threadIdx.x;
    int nth = gridDim.x * blockDim.x;

    for (int k = tid; k < NFFT; k += nth)
        d_hann[k] = (float)(0.5 - 0.5 * cospi((double)k / 200.0));

    // B2dft: rows n<402: even=cos, odd=sin of 2*pi*(n/2)*k/400; pad zero
    for (int idx = tid; idx < NP_DFT * KP_DFT; idx += nth) {
        int n = idx / KP_DFT, k = idx % KP_DFT;
        float v = 0.f;
        if (n < 2 * NBINS && k < NFFT) {
            int m = n >> 1;
            int ph = (m * k) % 400;
            double s, c;
            sincospi((double)ph / 200.0, &s, &c);
            v = (float)((n & 1) ? s : c);
        }
        splitw(d_B2dft, (size_t)n * (2 * KP_DFT), KP_DFT, k, v);
    }

    // B2mel[m][k] = fb[k][m]
    const double mel_max = 2595.0 * log10(1.0 + 8000.0 / 700.0);
    for (int idx = tid; idx < 128 * KP_MEL; idx += nth) {
        int m = idx / KP_MEL, k = idx % KP_MEL;
        float v = 0.f;
        if (k < NBINS) {
            double freq = 40.0 * (double)k;
            double f0 = 700.0 * (pow(10.0, (mel_max * (double)(m    ) / 129.0) / 2595.0) - 1.0);
            double f1 = 700.0 * (pow(10.0, (mel_max * (double)(m + 1) / 129.0) / 2595.0) - 1.0);
            double f2 = 700.0 * (pow(10.0, (mel_max * (double)(m + 2) / 129.0) / 2595.0) - 1.0);
            double dn = (freq - f0) / (f1 - f0);
            double up = (f2 - freq) / (f2 - f1);
            double t = dn < up ? dn : up;
            if (t < 0.0) t = 0.0;
            v = (float)t;
        }
        splitw(d_B2mel, (size_t)m * (2 * KP_MEL), KP_MEL, k, v);
    }

    // B2conv[o][q], q = kk*128+i
    for (int idx = tid; idx < 128 * KP_CONV; idx += nth) {
        int o = idx / KP_CONV, q = idx % KP_CONV;
        int kk = q >> 7, i = q & 127;
        float v = conv_w[o * 384 + i * 3 + kk];
        splitw(d_B2conv, (size_t)o * (2 * KP_CONV), KP_CONV, q, v);
    }

    // B2W[n][k] = W[k*512+n]
    for (int idx = tid; idx < G4 * KP_G; idx += nth) {
        int n = idx / KP_G, k = idx % KP_G;
        splitw(d_B2W1, (size_t)n * (2 * KP_G), KP_G, k, W1[k * G4 + n]);
        splitw(d_B2W2, (size_t)n * (2 * KP_G), KP_G, k, W2[k * G4 + n]);
    }

    // A2mel pad cols [201,224) must stay zero
    for (int idx = tid; idx < R1 * (KP_MEL - NBINS); idx += nth) {
        int r = idx / (KP_MEL - NBINS), k = NBINS + idx % (KP_MEL - NBINS);
        d_A2mel[(size_t)r * (2 * KP_MEL) + k] = __float2bfloat16(0.f);
        d_A2mel[(size_t)r * (2 * KP_MEL) + KP_MEL + k] = __float2bfloat16(0.f);
    }
}

// ---------------- windowed frames -> split-bf16 A for DFT GEMM ----------------
__global__ void k_window(const float* __restrict__ x) {
    int f = blockIdx.x, b = blockIdx.y, tid = threadIdx.x;
    size_t row = (size_t)(b * NFRAMES + f) * (2 * KP_DFT);
    for (int k = tid; k < KP_DFT; k += blockDim.x) {
        float v = 0.f;
        if (k < NFFT) {
            int p = f * HOP + k - 200;
            int i = (p < 0) ? -p : ((p >= TLEN) ? (2 * TLEN - 2 - p) : p);
            v = x[(size_t)b * TLEN + i] * d_hann[k];
        }
        __nv_bfloat16 h = __float2bfloat16(v);
        d_A2dft[row + k] = h;
        d_A2dft[row + KP_DFT + k] = __float2bfloat16(v - __bfloat162float(h));
    }
}

// ---------------- bf16x2-split tensor-core GEMM (3 K-segments) ----------------
// A2: (M x 2Kp) [hi|lo], B2: (Np x 2Kp) [hi|lo] (B stored n-major = col-major B)
// C = Ah@Bh + Ah@Bl + Al@Bh
// mode 0: outF[r*ldc+c] = acc (+bias)
// mode 1: power pack: p = C[2k]^2 + C[2k+1]^2, split-write to outP (guard k<Nreal)
// mode 2: split pack: v = acc + bias, split-write to outP at col c
__global__ void __launch_bounds__(256)
k_gemm(const __nv_bfloat16* __restrict__ A2, const __nv_bfloat16* __restrict__ B2,
       int Kp, const float* __restrict__ bias, int mode,
       float* __restrict__ outF, int ldc, int Nreal,
       __nv_bfloat16* __restrict__ outP, int KpOut) {
    __shared__ __nv_bfloat16 As[128][40];
    __shared__ __nv_bfloat16 Bs[64][40];
    int tid = threadIdx.x, lane = tid & 31, w = tid >> 5;
    int wm = w >> 1, wn = w & 1;
    int m0 = blockIdx.y * 128, n0 = blockIdx.x * 64;
    int g = lane >> 2, t = lane & 3;
    int strideA = 2 * Kp;

    float acc[2][4][4];
    #pragma unroll
    for (int i = 0; i < 2; i++)
        #pragma unroll
        for (int j = 0; j < 4; j++)
            #pragma unroll
            for (int q = 0; q < 4; q++) acc[i][j][q] = 0.f;

    int la_row0 = tid >> 2, la_kc = (tid & 3) << 3;      // +64 rows for second chunk
    int lb_row = tid >> 2, lb_kc = (tid & 3) << 3;

    #pragma unroll 1
    for (int seg = 0; seg < 3; seg++) {
        int aoff = (seg == 2) ? Kp : 0;
        int boff = (seg == 1) ? Kp : 0;
        const __nv_bfloat16* Ab = A2 + (size_t)m0 * strideA + aoff;
        const __nv_bfloat16* Bb = B2 + (size_t)n0 * strideA + boff;
        #pragma unroll 1
        for (int kk = 0; kk < Kp; kk += 32) {
            __syncthreads();
            #pragma unroll
            for (int i = 0; i < 2; i++) {
                int row = la_row0 + i * 64;
                uint4 v = *(const uint4*)(Ab + (size_t)row * strideA + kk + la_kc);
                *(uint4*)&As[row][la_kc] = v;
            }
            {
                uint4 v = *(const uint4*)(Bb + (size_t)lb_row * strideA + kk + lb_kc);
                *(uint4*)&Bs[lb_row][lb_kc] = v;
            }
            __syncthreads();
            #pragma unroll
            for (int ko = 0; ko < 32; ko += 16) {
                unsigned a[2][4], bfr[4][2];
                #pragma unroll
                for (int i = 0; i < 2; i++) {
                    int r = wm * 32 + i * 16;
                    a[i][0] = *(const unsigned*)&As[r + g][ko + 2 * t];
                    a[i][1] = *(const unsigned*)&As[r + g + 8][ko + 2 * t];
                    a[i][2] = *(const unsigned*)&As[r + g][ko + 2 * t + 8];
                    a[i][3] = *(const unsigned*)&As[r + g + 8][ko + 2 * t + 8];
                }
                #pragma unroll
                for (int j = 0; j < 4; j++) {
                    int bn = wn * 32 + j * 8 + g;
                    bfr[j][0] = *(const unsigned*)&Bs[bn][ko + 2 * t];
                    bfr[j][1] = *(const unsigned*)&Bs[bn][ko + 2 * t + 8];
                }
                #pragma unroll
                for (int i = 0; i < 2; i++)
                    #pragma unroll
                    for (int j = 0; j < 4; j++) {
                        asm volatile(
                            "mma.sync.aligned.m16n8k16.row.col.f32.bf16.bf16.f32 "
                            "{%0,%1,%2,%3}, {%4,%5,%6,%7}, {%8,%9}, {%0,%1,%2,%3};"
                            : "+f"(acc[i][j][0]), "+f"(acc[i][j][1]),
                              "+f"(acc[i][j][2]), "+f"(acc[i][j][3])
                            : "r"(a[i][0]), "r"(a[i][1]), "r"(a[i][2]), "r"(a[i][3]),
                              "r"(bfr[j][0]), "r"(bfr[j][1]));
                    }
            }
        }
    }

    // epilogue
    #pragma unroll
    for (int i = 0; i < 2; i++) {
        int r = m0 + wm * 32 + i * 16 + g;
        #pragma unroll
        for (int j = 0; j < 4; j++) {
            int c = n0 + wn * 32 + j * 8 + 2 * t;
            float v00 = acc[i][j][0], v01 = acc[i][j][1];
            float v10 = acc[i][j][2], v11 = acc[i][j][3];
            if (mode == 0) {
                float b0 = bias ? bias[c] : 0.f, b1 = bias ? bias[c + 1] : 0.f;
                outF[(size_t)r * ldc + c]           = v00 + b0;
                outF[(size_t)r * ldc + c + 1]       = v01 + b1;
                outF[(size_t)(r + 8) * ldc + c]     = v10 + b0;
                outF[(size_t)(r + 8) * ldc + c + 1] = v11 + b1;
            } else if (mode == 1) {
                int k = c >> 1;
                if (k < Nreal) {
                    splitw(outP, (size_t)r * (2 * KpOut), KpOut, k, v00 * v00 + v01 * v01);
                    splitw(outP, (size_t)(r + 8) * (2 * KpOut), KpOut, k, v10 * v10 + v11 * v11);
                }
            } else {
                float b0 = bias ? bias[c] : 0.f, b1 = bias ? bias[c + 1] : 0.f;
                splitw(outP, (size_t)r * (2 * KpOut), KpOut, c, v00 + b0);
                splitw(outP, (size_t)r * (2 * KpOut), KpOut, c + 1, v01 + b1);
                splitw(outP, (size_t)(r + 8) * (2 * KpOut), KpOut, c, v10 + b0);
                splitw(outP, (size_t)(r + 8) * (2 * KpOut), KpOut, c + 1, v11 + b1);
            }
        }
    }
}

// ---------------- mel -> im2col split pack for conv GEMM ----------------
__global__ void k_pack_conv() {
    size_t tid = (size_t)blockIdx.x * blockDim.x + threadIdx.x;
    size_t nth = (size_t)gridDim.x * blockDim.x;
    for (size_t idx = tid; idx < (size_t)R2 * 384; idx += nth) {
        int r = (int)(idx / 384), q = (int)(idx % 384);
        int b = r / TSTEPS, tt = r % TSTEPS;
        int kk = q >> 7, m = q & 127;
        float v = d_mel[(size_t)(b * NFRAMES + tt + kk) * NMELS + m];
        splitw(d_A2conv, (size_t)r * (2 * KP_CONV), KP_CONV, q, v);
    }
}

// ---------------- persistent LSTM (8 batch rows / block), optional split pack ----------------
__global__ void k_lstm(const float* __restrict__ gx, const float* __restrict__ U,
                       float* __restrict__ hout, __nv_bfloat16* __restrict__ hsplit) {
    __shared__ float hb[8][128];
    __shared__ float cb[8][128];
    __shared__ float gb[8][G4];
    int tid = threadIdx.x;
    int b0 = blockIdx.x * 8;
    for (int i = tid; i < 8 * 128; i += 512) { (&hb[0][0])[i] = 0.f; (&cb[0][0])[i] = 0.f; }
    __syncthreads();

    for (int t = 0; t < TSTEPS; t++) {
        int j = tid;
        float acc[8];
        #pragma unroll
        for (int r = 0; r < 8; r++)
            acc[r] = gx[((size_t)(b0 + r) * TSTEPS + t) * G4 + j];
        #pragma unroll 4
        for (int k = 0; k < 128; k += 4) {
            float u0 = U[(k + 0) * G4 + j];
            float u1 = U[(k + 1) * G4 + j];
            float u2 = U[(k + 2) * G4 + j];
            float u3 = U[(k + 3) * G4 + j];
            #pragma unroll
            for (int r = 0; r < 8; r++) {
                float4 h4 = *reinterpret_cast<const float4*>(&hb[r][k]);
                acc[r] += h4.x * u0 + h4.y * u1 + h4.z * u2 + h4.w * u3;
            }
        }
        #pragma unroll
        for (int r = 0; r < 8; r++) gb[r][j] = acc[r];
        __syncthreads();
        #pragma unroll
        for (int s = 0; s < 2; s++) {
            int ui = tid + s * 512;
            int r = ui >> 7, col = ui & 127;
            float gi = gb[r][col];
            float gf = gb[r][128 + col];
            float gg = gb[r][256 + col];
            float go = gb[r][384 + col];
            float i_ = sigf(gi), f_ = sigf(gf), g_ = tanhf_acc(gg), o_ = sigf(go);
            float c = f_ * cb[r][col] + i_ * g_;
            float h = o_ * tanhf_acc(c);
            cb[r][col] = c;
            hb[r][col] = h;
            size_t row = (size_t)(b0 + r) * TSTEPS + t;
            hout[row * 128 + col] = h;
            if (hsplit) splitw(hsplit, row * (2 * KP_G), KP_G, col, h);
        }
        __syncthreads();
    }
}

// ---------------- time-mean ----------------
__global__ void k_mean(const float* __restrict__ h2) {
    int b = blockIdx.x, k = threadIdx.x;
    float s = 0.f;
    for (int t = 0; t < TSTEPS; t++)
        s += h2[((size_t)b * TSTEPS + t) * 128 + k];
    d_hmean[b * 128 + k] = s * (1.0f / (float)TSTEPS);
}

// ---------------- small fp32 SGEMM for fc/proj ----------------
__global__ void k_sgemm(const float* __restrict__ A, const float* __restrict__ Bm,
                        float* __restrict__ C, const float* __restrict__ bias,
                        int M, int N, int K) {
    __shared__ float As[8][68];
    __shared__ float Bs[8][64];
    int tid = threadIdx.x;
    int m0 = blockIdx.y * 64, n0 = blockIdx.x * 64;
    int tm = tid & 15, tn = tid >> 4;
    float acc[4][8];
    #pragma unroll
    for (int i = 0; i < 4; i++)
        #pragma unroll
        for (int j = 0; j < 8; j++) acc[i][j] = 0.f;
    for (int kk = 0; kk < K; kk += 8) {
        #pragma unroll
        for (int i = 0; i < 4; i++) {
            int l = tid + i * 128, m = l >> 3, k = l & 7;
            int gm = m0 + m, gk = kk + k;
            As[k][m] = (gm < M && gk < K) ? A[(size_t)gm * K + gk] : 0.f;
        }
        #pragma unroll
        for (int i = 0; i < 4; i++) {
            int l = tid + i * 128, k = l >> 6, n = l & 63;
            int gk = kk + k, gn = n0 + n;
            Bs[k][n] = (gk < K && gn < N) ? Bm[(size_t)gk * N + gn] : 0.f;
        }
        __syncthreads();
        #pragma unroll
        for (int k = 0; k < 8; k++) {
            float a[4], bv[8];
            #pragma unroll
            for (int i = 0; i < 4; i++) a[i] = As[k][tm * 4 + i];
            #pragma unroll
            for (int j = 0; j < 8; j++) bv[j] = Bs[k][tn * 8 + j];
            #pragma unroll
            for (int i = 0; i < 4; i++)
                #pragma unroll
                for (int j = 0; j < 8; j++) acc[i][j] += a[i] * bv[j];
        }
        __syncthreads();
    }
    #pragma unroll
    for (int i = 0; i < 4; i++) {
        int gm = m0 + tm * 4 + i;
        if (gm >= M) continue;
        #pragma unroll
        for (int j = 0; j < 8; j++) {
            int gn = n0 + tn * 8 + j;
            if (gn < N) C[(size_t)gm * N + gn] = acc[i][j] + (bias ? bias[gn] : 0.f);
        }
    }
}

// ---------------- launch ----------------
extern "C" void kernel_launch(void* const* d_in, const int* in_sizes, int n_in,
                              void* d_out, int out_size) {
    const float* x      = (const float*)d_in[0];
    const float* conv_w = (const float*)d_in[1];
    const float* conv_b = (const float*)d_in[2];
    const float* W1     = (const float*)d_in[3];
    const float* U1     = (const float*)d_in[4];
    const float* b1     = (const float*)d_in[5];
    const float* W2     = (const float*)d_in[6];
    const float* U2     = (const float*)d_in[7];
    const float* b2     = (const float*)d_in[8];
    const float* fc1_w  = (const float*)d_in[9];
    const float* fc1_b  = (const float*)d_in[10];
    const float* proj_w = (const float*)d_in[11];
    const float* proj_b = (const float*)d_in[12];
    float* out = (float*)d_out;

    __nv_bfloat16 *pA2dft, *pB2dft, *pA2mel, *pB2mel, *pA2conv, *pB2conv, *pA2g, *pB2W1, *pB2W2, *pH1s;
    float *pMel, *pG, *pH2, *pHmean, *pHfc;
    cudaGetSymbolAddress((void**)&pA2dft,  d_A2dft);
    cudaGetSymbolAddress((void**)&pB2dft,  d_B2dft);
    cudaGetSymbolAddress((void**)&pA2mel,  d_A2mel);
    cudaGetSymbolAddress((void**)&pB2mel,  d_B2mel);
    cudaGetSymbolAddress((void**)&pA2conv, d_A2conv);
    cudaGetSymbolAddress((void**)&pB2conv, d_B2conv);
    cudaGetSymbolAddress((void**)&pA2g,    d_A2g);
    cudaGetSymbolAddress((void**)&pB2W1,   d_B2W1);
    cudaGetSymbolAddress((void**)&pB2W2,   d_B2W2);
    cudaGetSymbolAddress((void**)&pH1s,    d_h1s);
    cudaGetSymbolAddress((void**)&pMel,    d_mel);
    cudaGetSymbolAddress((void**)&pG,      d_g);
    cudaGetSymbolAddress((void**)&pH2,     d_h2);
    cudaGetSymbolAddress((void**)&pHmean,  d_hmean);
    cudaGetSymbolAddress((void**)&pHfc,    d_hfc);

    k_precompute<<<128, 256>>>(conv_w, W1, W2);
    k_window<<<dim3(NFRAMES, BATCH), 256>>>(x);

    // DFT: (R1 x 402) = A2dft @ B2dft, epilogue -> power split-pack into A2mel
    k_gemm<<<dim3(NP_DFT / 64, R1 / 128), 256>>>(pA2dft, pB2dft, KP_DFT, nullptr, 1,
                                                 nullptr, 0, NBINS, pA2mel, KP_MEL);
    // mel: (R1 x 128) fp32
    k_gemm<<<dim3(2, R1 / 128), 256>>>(pA2mel, pB2mel, KP_MEL, nullptr, 0,
                                       pMel, NMELS, NMELS, nullptr, 0);
    k_pack_conv<<<2048, 256>>>();
    // conv: (R2 x 128) + conv_b, epilogue split-pack into A2g
    k_gemm<<<dim3(2, R2 / 128), 256>>>(pA2conv, pB2conv, KP_CONV, conv_b, 2,
                                       nullptr, 0, 128, pA2g, KP_G);
    // g1: (R2 x 512) fp32
    k_gemm<<<dim3(8, R2 / 128), 256>>>(pA2g, pB2W1, KP_G, b1, 0,
                                       pG, G4, G4, nullptr, 0);
    k_lstm<<<BATCH / 8, 512>>>(pG, U1, pH2 /*dummy*/, pH1s);
    // g2: (R2 x 512) fp32
    k_gemm<<<dim3(8, R2 / 128), 256>>>(pH1s, pB2W2, KP_G, b2, 0,
                                       pG, G4, G4, nullptr, 0);
    k_lstm<<<BATCH / 8, 512>>>(pG, U2, pH2, nullptr);

    k_mean<<<BATCH, 128>>>(pH2);
    k_sgemm<<<dim3(2, BATCH / 64), 128>>>(pHmean, fc1_w, pHfc, fc1_b, BATCH, 128, 128);
    k_sgemm<<<dim3(1, BATCH / 64), 128>>>(pHfc, proj_w, out, proj_b, BATCH, 35, 128);
}